// round 1
// baseline (speedup 1.0000x reference)
#include <cuda_runtime.h>
#include <math.h>

#define B   32
#define T   2048
#define H   1024
#define OUT 256

#define CHUNK  64                 // t-rows per block in main pass
#define NCHUNK (T / CHUNK)        // 32 chunks
#define RPW    (CHUNK / 8)        // rows per warp (8 warps/block)
#define JC     64                 // j-chunks in final GEMM (2048/32)

// ---- scratch (__device__ globals; no allocation allowed) ----
__device__ float d_htp[4 * B * H];                    // h_t partials (4 h-chunks)
__device__ float d_ht [B * H];                        // h_t
__device__ float d_v  [B * H];                        // v[b] = W1 @ h_t[b]
__device__ float d_scr[(size_t)B * NCHUNK * (H + 2)]; // per-chunk (s[1024], m, d)
__device__ float d_ctx[B * H];                        // context vector
__device__ float d_fp [(size_t)JC * B * OUT];         // final GEMM partials

// ================= h_t partial: h_t[b,k] += sum_{h in chunk} hs_last[b,h]*W1[h,k]
// grid (32 k-tiles of 32, 4 h-chunks of 256), 256 threads = 32 k x 8 b-groups(4 b)
__global__ void ht_partial_kernel(const float* __restrict__ hs,
                                  const float* __restrict__ W1) {
    int kt = blockIdx.x, hc = blockIdx.y;
    int tid = threadIdx.x;
    int kl = tid & 31, bg = tid >> 5;
    __shared__ float hsl[B][256];
    int h0 = hc * 256;
    for (int i = tid; i < B * 256; i += 256) {
        int b = i >> 8, hh = i & 255;
        hsl[b][hh] = hs[((size_t)b * T + (T - 1)) * H + h0 + hh];
    }
    __syncthreads();
    int k = kt * 32 + kl;
    int b0 = bg * 4;
    float a0 = 0.f, a1 = 0.f, a2 = 0.f, a3 = 0.f;
    const float* w1p = W1 + (size_t)h0 * H + k;
#pragma unroll 8
    for (int hh = 0; hh < 256; hh++) {
        float w = w1p[(size_t)hh * H];
        a0 = fmaf(hsl[b0 + 0][hh], w, a0);
        a1 = fmaf(hsl[b0 + 1][hh], w, a1);
        a2 = fmaf(hsl[b0 + 2][hh], w, a2);
        a3 = fmaf(hsl[b0 + 3][hh], w, a3);
    }
    d_htp[((size_t)hc * B + b0 + 0) * H + k] = a0;
    d_htp[((size_t)hc * B + b0 + 1) * H + k] = a1;
    d_htp[((size_t)hc * B + b0 + 2) * H + k] = a2;
    d_htp[((size_t)hc * B + b0 + 3) * H + k] = a3;
}

// ================= h_t reduce (+ bias b1)
__global__ void ht_reduce_kernel(const float* __restrict__ b1) {
    int idx = blockIdx.x * 256 + threadIdx.x;   // 32768 total
    int b = idx >> 10, k = idx & (H - 1);
    float a = b1[k];
#pragma unroll
    for (int hc = 0; hc < 4; hc++) a += d_htp[((size_t)hc * B + b) * H + k];
    d_ht[(size_t)b * H + k] = a;
}

// ================= v[b,h] = dot(W1 row h, h_t[b])
// grid (128 h-tiles of 8, 8 b-groups of 4), 256 threads: warp = one h row
__global__ void v_kernel(const float* __restrict__ W1) {
    int ht8 = blockIdx.x, bg = blockIdx.y;
    int tid = threadIdx.x;
    int w = tid >> 5, lane = tid & 31;
    __shared__ float hts[4][H];
    for (int i = tid; i < 4 * H; i += 256) {
        int bi = i >> 10, k = i & (H - 1);
        hts[bi][k] = d_ht[(size_t)(bg * 4 + bi) * H + k];
    }
    __syncthreads();
    int h = ht8 * 8 + w;
    const float4* row = (const float4*)(W1 + (size_t)h * H);
    float a0 = 0.f, a1 = 0.f, a2 = 0.f, a3 = 0.f;
#pragma unroll
    for (int ki = 0; ki < 8; ki++) {
        float4 wv = row[ki * 32 + lane];
        int kb = (ki * 32 + lane) * 4;
        float4 t0 = *(const float4*)&hts[0][kb];
        float4 t1 = *(const float4*)&hts[1][kb];
        float4 t2 = *(const float4*)&hts[2][kb];
        float4 t3 = *(const float4*)&hts[3][kb];
        a0 = fmaf(wv.x, t0.x, fmaf(wv.y, t0.y, fmaf(wv.z, t0.z, fmaf(wv.w, t0.w, a0))));
        a1 = fmaf(wv.x, t1.x, fmaf(wv.y, t1.y, fmaf(wv.z, t1.z, fmaf(wv.w, t1.w, a1))));
        a2 = fmaf(wv.x, t2.x, fmaf(wv.y, t2.y, fmaf(wv.z, t2.z, fmaf(wv.w, t2.w, a2))));
        a3 = fmaf(wv.x, t3.x, fmaf(wv.y, t3.y, fmaf(wv.z, t3.z, fmaf(wv.w, t3.w, a3))));
    }
#pragma unroll
    for (int off = 16; off; off >>= 1) {
        a0 += __shfl_xor_sync(0xffffffffu, a0, off);
        a1 += __shfl_xor_sync(0xffffffffu, a1, off);
        a2 += __shfl_xor_sync(0xffffffffu, a2, off);
        a3 += __shfl_xor_sync(0xffffffffu, a3, off);
    }
    if (lane == 0) {
        d_v[(size_t)(bg * 4 + 0) * H + h] = a0;
        d_v[(size_t)(bg * 4 + 1) * H + h] = a1;
        d_v[(size_t)(bg * 4 + 2) * H + h] = a2;
        d_v[(size_t)(bg * 4 + 3) * H + h] = a3;
    }
}

// ================= main streaming pass: score + online softmax + context accum
// grid (NCHUNK, B), 256 threads (8 warps x RPW rows each)
__global__ void __launch_bounds__(256) main_pass_kernel(const float* __restrict__ hs) {
    int chunk = blockIdx.x;
    int b = blockIdx.y;
    int tid = threadIdx.x;
    int w = tid >> 5, lane = tid & 31;

    const float4* vv = (const float4*)(d_v + (size_t)b * H);
    float4 vr[8];
#pragma unroll
    for (int i = 0; i < 8; i++) vr[i] = vv[i * 32 + lane];

    float4 sa[8];
#pragma unroll
    for (int i = 0; i < 8; i++) sa[i] = make_float4(0.f, 0.f, 0.f, 0.f);
    float m = -INFINITY, d = 0.f;

    int t0 = chunk * CHUNK + w * RPW;
    for (int r = 0; r < RPW; r++) {
        const float4* row = (const float4*)(hs + ((size_t)b * T + t0 + r) * H);
        float4 val[8];
#pragma unroll
        for (int i = 0; i < 8; i++) val[i] = row[i * 32 + lane];
        float dot = 0.f;
#pragma unroll
        for (int i = 0; i < 8; i++) {
            dot = fmaf(val[i].x, vr[i].x, dot);
            dot = fmaf(val[i].y, vr[i].y, dot);
            dot = fmaf(val[i].z, vr[i].z, dot);
            dot = fmaf(val[i].w, vr[i].w, dot);
        }
#pragma unroll
        for (int off = 16; off; off >>= 1) dot += __shfl_xor_sync(0xffffffffu, dot, off);
        float mn = fmaxf(m, dot);
        float sc = __expf(m - mn);      // 0 on first row (m=-inf)
        float wt = __expf(dot - mn);
        d = d * sc + wt;
#pragma unroll
        for (int i = 0; i < 8; i++) {
            sa[i].x = fmaf(sa[i].x, sc, wt * val[i].x);
            sa[i].y = fmaf(sa[i].y, sc, wt * val[i].y);
            sa[i].z = fmaf(sa[i].z, sc, wt * val[i].z);
            sa[i].w = fmaf(sa[i].w, sc, wt * val[i].w);
        }
        m = mn;
    }

    // block combine across 8 warps
    __shared__ float sm[8][H];
    __shared__ float smm[8], smd[8];
    float4* smrow = (float4*)sm[w];
#pragma unroll
    for (int i = 0; i < 8; i++) smrow[i * 32 + lane] = sa[i];
    if (lane == 0) { smm[w] = m; smd[w] = d; }
    __syncthreads();

    float M = smm[0];
#pragma unroll
    for (int i = 1; i < 8; i++) M = fmaxf(M, smm[i]);
    float wgt[8];
    float D = 0.f;
#pragma unroll
    for (int i = 0; i < 8; i++) { wgt[i] = __expf(smm[i] - M); D += wgt[i] * smd[i]; }

    float* base = d_scr + (size_t)(b * NCHUNK + chunk) * (H + 2);
    for (int h = tid; h < H; h += 256) {
        float a = 0.f;
#pragma unroll
        for (int i = 0; i < 8; i++) a = fmaf(wgt[i], sm[i][h], a);
        base[h] = a;
    }
    if (tid == 0) { base[H] = M; base[H + 1] = D; }
}

// ================= grid combine: ctx[b,h] = sum_c w_c * s_c[h] / D
__global__ void combine_kernel() {
    int b = blockIdx.x;
    int tid = threadIdx.x;
    __shared__ float mb[NCHUNK], db[NCHUNK], wc[NCHUNK];
    if (tid < NCHUNK) {
        const float* base = d_scr + (size_t)(b * NCHUNK + tid) * (H + 2);
        mb[tid] = base[H];
        db[tid] = base[H + 1];
    }
    __syncthreads();
    float M = mb[0];
#pragma unroll
    for (int c = 1; c < NCHUNK; c++) M = fmaxf(M, mb[c]);
    if (tid < NCHUNK) wc[tid] = __expf(mb[tid] - M);
    __syncthreads();
    float D = 0.f;
#pragma unroll
    for (int c = 0; c < NCHUNK; c++) D += wc[c] * db[c];
    float inv = 1.f / D;
    for (int h = tid; h < H; h += 256) {
        float a = 0.f;
        for (int c = 0; c < NCHUNK; c++)
            a = fmaf(wc[c], d_scr[(size_t)(b * NCHUNK + c) * (H + 2) + h], a);
        d_ctx[(size_t)b * H + h] = a * inv;
    }
}

// ================= final GEMM partials: [ctx, h_t] @ Wv, j-chunked
// grid (JC, 4 b-groups of 8), 256 threads = one output column o each
__global__ void final_partial_kernel(const float* __restrict__ Wv) {
    int jc = blockIdx.x, bgrp = blockIdx.y;
    int tid = threadIdx.x;          // o
    __shared__ float pa[8][32];
    {
        int bi = tid >> 5, jj = tid & 31;
        int bb = bgrp * 8 + bi;
        int j = jc * 32 + jj;
        pa[bi][jj] = (j < H) ? d_ctx[(size_t)bb * H + j]
                             : d_ht[(size_t)bb * H + (j - H)];
    }
    __syncthreads();
    float acc[8];
#pragma unroll
    for (int bi = 0; bi < 8; bi++) acc[bi] = 0.f;
    const float* wp = Wv + (size_t)(jc * 32) * OUT + tid;
#pragma unroll 4
    for (int jj = 0; jj < 32; jj++) {
        float wv = wp[(size_t)jj * OUT];
#pragma unroll
        for (int bi = 0; bi < 8; bi++) acc[bi] = fmaf(pa[bi][jj], wv, acc[bi]);
    }
#pragma unroll
    for (int bi = 0; bi < 8; bi++)
        d_fp[((size_t)jc * B + bgrp * 8 + bi) * OUT + tid] = acc[bi];
}

// ================= final reduce + bias + tanh
__global__ void final_reduce_kernel(const float* __restrict__ bv, float* __restrict__ out) {
    int b = blockIdx.x;
    int o = threadIdx.x;
    float a = bv[o];
#pragma unroll 8
    for (int jc = 0; jc < JC; jc++) a += d_fp[((size_t)jc * B + b) * OUT + o];
    out[(size_t)b * OUT + o] = tanhf(a);
}

extern "C" void kernel_launch(void* const* d_in, const int* in_sizes, int n_in,
                              void* d_out, int out_size) {
    const float* hs = (const float*)d_in[0];
    const float* W1 = (const float*)d_in[1];
    const float* b1 = (const float*)d_in[2];
    const float* Wv = (const float*)d_in[3];
    const float* bv = (const float*)d_in[4];
    float* out = (float*)d_out;

    ht_partial_kernel<<<dim3(32, 4), 256>>>(hs, W1);
    ht_reduce_kernel<<<128, 256>>>(b1);
    v_kernel<<<dim3(128, 8), 256>>>(W1);
    main_pass_kernel<<<dim3(NCHUNK, B), 256>>>(hs);
    combine_kernel<<<B, 256>>>();
    final_partial_kernel<<<dim3(JC, 4), 256>>>(Wv);
    final_reduce_kernel<<<B, OUT>>>(bv, out);
}

// round 2
// speedup vs baseline: 1.2892x; 1.2892x over previous
#include <cuda_runtime.h>
#include <math.h>

#define B   32
#define T   2048
#define H   1024
#define OUT 256

#define CHUNK  64                 // t-rows per block in main pass
#define NCHUNK (T / CHUNK)        // 32 chunks
#define RPW    (CHUNK / 8)        // rows per warp (8 warps/block)
#define JC     64                 // j-chunks in final GEMM (2048/32)
#define HC     16                 // h-chunks for ht partial (64 each)

// ---- scratch (__device__ globals; no allocation allowed) ----
__device__ float d_htp[HC * B * H];                   // h_t partials
__device__ float d_ht [B * H];                        // h_t
__device__ float d_v  [B * H];                        // v[b] = W1 @ h_t[b]
__device__ float d_scr[(size_t)B * NCHUNK * (H + 2)]; // per-chunk (s[1024], m, d)
__device__ float d_ctx[B * H];                        // context vector
__device__ float d_fp [(size_t)JC * B * OUT];         // final GEMM partials

// ================= h_t partial: h_t[b,k] += sum_{h in chunk} hs_last[b,h]*W1[h,k]
// grid (32 k-tiles of 32, HC h-chunks of 64), 256 threads = 32 k x 8 b-groups(4 b)
__global__ void __launch_bounds__(256) ht_partial_kernel(const float* __restrict__ hs,
                                                         const float* __restrict__ W1) {
    int kt = blockIdx.x, hc = blockIdx.y;
    int tid = threadIdx.x;
    int kl = tid & 31, bg = tid >> 5;
    __shared__ float hsl[B][64];
    int h0 = hc * 64;
    for (int i = tid; i < B * 64; i += 256) {
        int b = i >> 6, hh = i & 63;
        hsl[b][hh] = hs[((size_t)b * T + (T - 1)) * H + h0 + hh];
    }
    __syncthreads();
    int k = kt * 32 + kl;
    int b0 = bg * 4;
    float a0 = 0.f, a1 = 0.f, a2 = 0.f, a3 = 0.f;
    const float* w1p = W1 + (size_t)h0 * H + k;
#pragma unroll 16
    for (int hh = 0; hh < 64; hh++) {
        float w = w1p[(size_t)hh * H];
        a0 = fmaf(hsl[b0 + 0][hh], w, a0);
        a1 = fmaf(hsl[b0 + 1][hh], w, a1);
        a2 = fmaf(hsl[b0 + 2][hh], w, a2);
        a3 = fmaf(hsl[b0 + 3][hh], w, a3);
    }
    d_htp[((size_t)hc * B + b0 + 0) * H + k] = a0;
    d_htp[((size_t)hc * B + b0 + 1) * H + k] = a1;
    d_htp[((size_t)hc * B + b0 + 2) * H + k] = a2;
    d_htp[((size_t)hc * B + b0 + 3) * H + k] = a3;
}

// ================= h_t reduce (+ bias b1): 32768 outputs
__global__ void __launch_bounds__(256) ht_reduce_kernel(const float* __restrict__ b1) {
    int idx = blockIdx.x * 256 + threadIdx.x;
    int b = idx >> 10, k = idx & (H - 1);
    float a = b1[k];
#pragma unroll
    for (int hc = 0; hc < HC; hc++) a += d_htp[((size_t)hc * B + b) * H + k];
    d_ht[(size_t)b * H + k] = a;
}

// ================= v[b,h] = dot(W1 row h, h_t[b])
// grid (128 h-tiles of 8, 8 b-groups of 4), 256 threads: warp = one h row
__global__ void __launch_bounds__(256) v_kernel(const float* __restrict__ W1) {
    int ht8 = blockIdx.x, bg = blockIdx.y;
    int tid = threadIdx.x;
    int w = tid >> 5, lane = tid & 31;
    __shared__ float hts[4][H];
    for (int i = tid; i < 4 * H; i += 256) {
        int bi = i >> 10, k = i & (H - 1);
        hts[bi][k] = d_ht[(size_t)(bg * 4 + bi) * H + k];
    }
    __syncthreads();
    int h = ht8 * 8 + w;
    const float4* row = (const float4*)(W1 + (size_t)h * H);
    float a0 = 0.f, a1 = 0.f, a2 = 0.f, a3 = 0.f;
#pragma unroll
    for (int ki = 0; ki < 8; ki++) {
        float4 wv = row[ki * 32 + lane];
        int kb = (ki * 32 + lane) * 4;
        float4 t0 = *(const float4*)&hts[0][kb];
        float4 t1 = *(const float4*)&hts[1][kb];
        float4 t2 = *(const float4*)&hts[2][kb];
        float4 t3 = *(const float4*)&hts[3][kb];
        a0 = fmaf(wv.x, t0.x, fmaf(wv.y, t0.y, fmaf(wv.z, t0.z, fmaf(wv.w, t0.w, a0))));
        a1 = fmaf(wv.x, t1.x, fmaf(wv.y, t1.y, fmaf(wv.z, t1.z, fmaf(wv.w, t1.w, a1))));
        a2 = fmaf(wv.x, t2.x, fmaf(wv.y, t2.y, fmaf(wv.z, t2.z, fmaf(wv.w, t2.w, a2))));
        a3 = fmaf(wv.x, t3.x, fmaf(wv.y, t3.y, fmaf(wv.z, t3.z, fmaf(wv.w, t3.w, a3))));
    }
#pragma unroll
    for (int off = 16; off; off >>= 1) {
        a0 += __shfl_xor_sync(0xffffffffu, a0, off);
        a1 += __shfl_xor_sync(0xffffffffu, a1, off);
        a2 += __shfl_xor_sync(0xffffffffu, a2, off);
        a3 += __shfl_xor_sync(0xffffffffu, a3, off);
    }
    if (lane == 0) {
        d_v[(size_t)(bg * 4 + 0) * H + h] = a0;
        d_v[(size_t)(bg * 4 + 1) * H + h] = a1;
        d_v[(size_t)(bg * 4 + 2) * H + h] = a2;
        d_v[(size_t)(bg * 4 + 3) * H + h] = a3;
    }
}

// ================= main streaming pass: score + online softmax + context accum
// grid (NCHUNK, B), 256 threads (8 warps x RPW rows each)
// v kept in SHARED (frees 32 regs -> 3 CTAs/SM instead of 2)
__global__ void __launch_bounds__(256) main_pass_kernel(const float* __restrict__ hs) {
    int chunk = blockIdx.x;
    int b = blockIdx.y;
    int tid = threadIdx.x;
    int w = tid >> 5, lane = tid & 31;

    __shared__ float4 vsh[H / 4];
    __shared__ float sm[8][H];
    __shared__ float smm[8], smd[8];

    vsh[tid] = ((const float4*)(d_v + (size_t)b * H))[tid];
    __syncthreads();

    float4 sa[8];
#pragma unroll
    for (int i = 0; i < 8; i++) sa[i] = make_float4(0.f, 0.f, 0.f, 0.f);
    float m = -INFINITY, d = 0.f;

    int t0 = chunk * CHUNK + w * RPW;
    for (int r = 0; r < RPW; r++) {
        const float4* row = (const float4*)(hs + ((size_t)b * T + t0 + r) * H);
        float4 val[8];
#pragma unroll
        for (int i = 0; i < 8; i++) val[i] = __ldcs(row + i * 32 + lane);
        float dot = 0.f;
#pragma unroll
        for (int i = 0; i < 8; i++) {
            float4 vv = vsh[i * 32 + lane];
            dot = fmaf(val[i].x, vv.x, dot);
            dot = fmaf(val[i].y, vv.y, dot);
            dot = fmaf(val[i].z, vv.z, dot);
            dot = fmaf(val[i].w, vv.w, dot);
        }
#pragma unroll
        for (int off = 16; off; off >>= 1) dot += __shfl_xor_sync(0xffffffffu, dot, off);
        float mn = fmaxf(m, dot);
        float sc = __expf(m - mn);      // 0 on first row (m=-inf)
        float wt = __expf(dot - mn);
        d = d * sc + wt;
#pragma unroll
        for (int i = 0; i < 8; i++) {
            sa[i].x = fmaf(sa[i].x, sc, wt * val[i].x);
            sa[i].y = fmaf(sa[i].y, sc, wt * val[i].y);
            sa[i].z = fmaf(sa[i].z, sc, wt * val[i].z);
            sa[i].w = fmaf(sa[i].w, sc, wt * val[i].w);
        }
        m = mn;
    }

    // block combine across 8 warps
    float4* smrow = (float4*)sm[w];
#pragma unroll
    for (int i = 0; i < 8; i++) smrow[i * 32 + lane] = sa[i];
    if (lane == 0) { smm[w] = m; smd[w] = d; }
    __syncthreads();

    float M = smm[0];
#pragma unroll
    for (int i = 1; i < 8; i++) M = fmaxf(M, smm[i]);
    float wgt[8];
    float D = 0.f;
#pragma unroll
    for (int i = 0; i < 8; i++) { wgt[i] = __expf(smm[i] - M); D += wgt[i] * smd[i]; }

    float* base = d_scr + (size_t)(b * NCHUNK + chunk) * (H + 2);
    for (int h = tid; h < H; h += 256) {
        float a = 0.f;
#pragma unroll
        for (int i = 0; i < 8; i++) a = fmaf(wgt[i], sm[i][h], a);
        base[h] = a;
    }
    if (tid == 0) { base[H] = M; base[H + 1] = D; }
}

// ================= grid combine: ctx[b,h] = sum_c w_c * s_c[h] / D
// grid (B, 4 quarters of 256 h), 256 threads; c loop fully unrolled (MLP 32)
__global__ void __launch_bounds__(256) combine_kernel() {
    int b = blockIdx.x, q = blockIdx.y;
    int tid = threadIdx.x;
    __shared__ float mb[NCHUNK], db[NCHUNK], wc[NCHUNK];
    if (tid < NCHUNK) {
        const float* base = d_scr + (size_t)(b * NCHUNK + tid) * (H + 2);
        mb[tid] = base[H];
        db[tid] = base[H + 1];
    }
    __syncthreads();
    float M = mb[0];
#pragma unroll
    for (int c = 1; c < NCHUNK; c++) M = fmaxf(M, mb[c]);
    if (tid < NCHUNK) wc[tid] = __expf(mb[tid] - M);
    __syncthreads();
    float D = 0.f;
#pragma unroll
    for (int c = 0; c < NCHUNK; c++) D += wc[c] * db[c];
    float inv = 1.f / D;
    int h = q * 256 + tid;
    float a = 0.f;
#pragma unroll
    for (int c = 0; c < NCHUNK; c++)
        a = fmaf(wc[c], d_scr[(size_t)(b * NCHUNK + c) * (H + 2) + h], a);
    d_ctx[(size_t)b * H + h] = a * inv;
}

// ================= final GEMM partials: [ctx, h_t] @ Wv, j-chunked
// grid (JC, 4 b-groups of 8), 256 threads = one output column o each
__global__ void __launch_bounds__(256) final_partial_kernel(const float* __restrict__ Wv) {
    int jc = blockIdx.x, bgrp = blockIdx.y;
    int tid = threadIdx.x;          // o
    __shared__ float pa[8][32];
    {
        int bi = tid >> 5, jj = tid & 31;
        int bb = bgrp * 8 + bi;
        int j = jc * 32 + jj;
        pa[bi][jj] = (j < H) ? d_ctx[(size_t)bb * H + j]
                             : d_ht[(size_t)bb * H + (j - H)];
    }
    __syncthreads();
    float acc[8];
#pragma unroll
    for (int bi = 0; bi < 8; bi++) acc[bi] = 0.f;
    const float* wp = Wv + (size_t)(jc * 32) * OUT + tid;
#pragma unroll 8
    for (int jj = 0; jj < 32; jj++) {
        float wv = wp[(size_t)jj * OUT];
#pragma unroll
        for (int bi = 0; bi < 8; bi++) acc[bi] = fmaf(pa[bi][jj], wv, acc[bi]);
    }
#pragma unroll
    for (int bi = 0; bi < 8; bi++)
        d_fp[((size_t)jc * B + bgrp * 8 + bi) * OUT + tid] = acc[bi];
}

// ================= final reduce + bias + tanh
__global__ void __launch_bounds__(256) final_reduce_kernel(const float* __restrict__ bv,
                                                           float* __restrict__ out) {
    int b = blockIdx.x;
    int o = threadIdx.x;
    float a = bv[o];
#pragma unroll 16
    for (int jc = 0; jc < JC; jc++) a += d_fp[((size_t)jc * B + b) * OUT + o];
    out[(size_t)b * OUT + o] = tanhf(a);
}

extern "C" void kernel_launch(void* const* d_in, const int* in_sizes, int n_in,
                              void* d_out, int out_size) {
    const float* hs = (const float*)d_in[0];
    const float* W1 = (const float*)d_in[1];
    const float* b1 = (const float*)d_in[2];
    const float* Wv = (const float*)d_in[3];
    const float* bv = (const float*)d_in[4];
    float* out = (float*)d_out;

    ht_partial_kernel<<<dim3(32, HC), 256>>>(hs, W1);
    ht_reduce_kernel<<<128, 256>>>(b1);
    v_kernel<<<dim3(128, 8), 256>>>(W1);
    main_pass_kernel<<<dim3(NCHUNK, B), 256>>>(hs);
    combine_kernel<<<dim3(B, 4), 256>>>();
    final_partial_kernel<<<dim3(JC, 4), 256>>>(Wv);
    final_reduce_kernel<<<B, OUT>>>(bv, out);
}

// round 3
// speedup vs baseline: 1.4891x; 1.1551x over previous
#include <cuda_runtime.h>
#include <math.h>

#define B   32
#define T   2048
#define H   1024
#define OUT 256

#define CHUNK  64                 // t-rows per block in main pass
#define NCHUNK (T / CHUNK)        // 32 chunks
#define JC     64                 // j-chunks in final GEMM (2048/32)
#define HC     16                 // h-chunks for ht partial (64 each)

// ---- scratch (__device__ globals; no allocation allowed) ----
__device__ float d_htp[HC * B * H];                   // h_t partials
__device__ float d_ht [B * H];                        // h_t
__device__ float d_v  [B * H];                        // v[b] = W1 @ h_t[b]
__device__ float d_scr[(size_t)B * NCHUNK * H];       // per-chunk context partials
__device__ float d_md [(size_t)B * NCHUNK * 2];       // per-chunk (m, d)
__device__ float d_ctx[B * H];                        // context vector
__device__ float d_fp [(size_t)JC * B * OUT];         // final GEMM partials

// ================= h_t partial: h_t[b,k] += sum_{h in chunk} hs_last[b,h]*W1[h,k]
__global__ void __launch_bounds__(256) ht_partial_kernel(const float* __restrict__ hs,
                                                         const float* __restrict__ W1) {
    int kt = blockIdx.x, hc = blockIdx.y;
    int tid = threadIdx.x;
    int kl = tid & 31, bg = tid >> 5;
    __shared__ float hsl[B][64];
    int h0 = hc * 64;
    for (int i = tid; i < B * 64; i += 256) {
        int b = i >> 6, hh = i & 63;
        hsl[b][hh] = hs[((size_t)b * T + (T - 1)) * H + h0 + hh];
    }
    __syncthreads();
    int k = kt * 32 + kl;
    int b0 = bg * 4;
    float a0 = 0.f, a1 = 0.f, a2 = 0.f, a3 = 0.f;
    const float* w1p = W1 + (size_t)h0 * H + k;
#pragma unroll 16
    for (int hh = 0; hh < 64; hh++) {
        float w = w1p[(size_t)hh * H];
        a0 = fmaf(hsl[b0 + 0][hh], w, a0);
        a1 = fmaf(hsl[b0 + 1][hh], w, a1);
        a2 = fmaf(hsl[b0 + 2][hh], w, a2);
        a3 = fmaf(hsl[b0 + 3][hh], w, a3);
    }
    d_htp[((size_t)hc * B + b0 + 0) * H + k] = a0;
    d_htp[((size_t)hc * B + b0 + 1) * H + k] = a1;
    d_htp[((size_t)hc * B + b0 + 2) * H + k] = a2;
    d_htp[((size_t)hc * B + b0 + 3) * H + k] = a3;
}

// ================= h_t reduce (+ bias b1): 32768 outputs
__global__ void __launch_bounds__(256) ht_reduce_kernel(const float* __restrict__ b1) {
    int idx = blockIdx.x * 256 + threadIdx.x;
    int b = idx >> 10, k = idx & (H - 1);
    float a = b1[k];
#pragma unroll
    for (int hc = 0; hc < HC; hc++) a += d_htp[((size_t)hc * B + b) * H + k];
    d_ht[(size_t)b * H + k] = a;
}

// ================= v[b,h] = dot(W1 row h, h_t[b])
__global__ void __launch_bounds__(256) v_kernel(const float* __restrict__ W1) {
    int ht8 = blockIdx.x, bg = blockIdx.y;
    int tid = threadIdx.x;
    int w = tid >> 5, lane = tid & 31;
    __shared__ float hts[4][H];
    for (int i = tid; i < 4 * H; i += 256) {
        int bi = i >> 10, k = i & (H - 1);
        hts[bi][k] = d_ht[(size_t)(bg * 4 + bi) * H + k];
    }
    __syncthreads();
    int h = ht8 * 8 + w;
    const float4* row = (const float4*)(W1 + (size_t)h * H);
    float a0 = 0.f, a1 = 0.f, a2 = 0.f, a3 = 0.f;
#pragma unroll
    for (int ki = 0; ki < 8; ki++) {
        float4 wv = row[ki * 32 + lane];
        int kb = (ki * 32 + lane) * 4;
        float4 t0 = *(const float4*)&hts[0][kb];
        float4 t1 = *(const float4*)&hts[1][kb];
        float4 t2 = *(const float4*)&hts[2][kb];
        float4 t3 = *(const float4*)&hts[3][kb];
        a0 = fmaf(wv.x, t0.x, fmaf(wv.y, t0.y, fmaf(wv.z, t0.z, fmaf(wv.w, t0.w, a0))));
        a1 = fmaf(wv.x, t1.x, fmaf(wv.y, t1.y, fmaf(wv.z, t1.z, fmaf(wv.w, t1.w, a1))));
        a2 = fmaf(wv.x, t2.x, fmaf(wv.y, t2.y, fmaf(wv.z, t2.z, fmaf(wv.w, t2.w, a2))));
        a3 = fmaf(wv.x, t3.x, fmaf(wv.y, t3.y, fmaf(wv.z, t3.z, fmaf(wv.w, t3.w, a3))));
    }
#pragma unroll
    for (int off = 16; off; off >>= 1) {
        a0 += __shfl_xor_sync(0xffffffffu, a0, off);
        a1 += __shfl_xor_sync(0xffffffffu, a1, off);
        a2 += __shfl_xor_sync(0xffffffffu, a2, off);
        a3 += __shfl_xor_sync(0xffffffffu, a3, off);
    }
    if (lane == 0) {
        d_v[(size_t)(bg * 4 + 0) * H + h] = a0;
        d_v[(size_t)(bg * 4 + 1) * H + h] = a1;
        d_v[(size_t)(bg * 4 + 2) * H + h] = a2;
        d_v[(size_t)(bg * 4 + 3) * H + h] = a3;
    }
}

// ================= main streaming pass (low-reg, block-per-row layout)
// grid (NCHUNK, B), 256 threads. Thread tid owns h-slice [4*tid, 4*tid+4).
// Block walks all CHUNK rows; per row: 4-elem partial dot -> warp reduce ->
// 1 barrier (double-buffered 8-float combine) -> block-uniform softmax update.
__global__ void __launch_bounds__(256) main_pass_kernel(const float* __restrict__ hs) {
    int chunk = blockIdx.x;
    int b = blockIdx.y;
    int tid = threadIdx.x;
    int w = tid >> 5, lane = tid & 31;

    __shared__ float part[2][8];

    float4 vr = ((const float4*)(d_v + (size_t)b * H))[tid];
    float4 sa = make_float4(0.f, 0.f, 0.f, 0.f);
    float m = -INFINITY, d = 0.f;

    const float4* base = (const float4*)(hs + ((size_t)b * T + (size_t)chunk * CHUNK) * H) + tid;

    float4 cur = __ldcs(base);
    float4 nxt = __ldcs(base + (H / 4));

    for (int r = 0; r < CHUNK; r++) {
        int rp = (r + 2 < CHUNK) ? r + 2 : CHUNK - 1;
        float4 nn = __ldcs(base + (size_t)rp * (H / 4));

        float p = fmaf(cur.x, vr.x, fmaf(cur.y, vr.y, fmaf(cur.z, vr.z, cur.w * vr.w)));
#pragma unroll
        for (int off = 16; off; off >>= 1) p += __shfl_xor_sync(0xffffffffu, p, off);
        if (lane == 0) part[r & 1][w] = p;
        __syncthreads();
        float dot = ((part[r & 1][0] + part[r & 1][1]) + (part[r & 1][2] + part[r & 1][3]))
                  + ((part[r & 1][4] + part[r & 1][5]) + (part[r & 1][6] + part[r & 1][7]));

        float mn = fmaxf(m, dot);
        float sc = __expf(m - mn);      // 0 on first row (m=-inf)
        float wt = __expf(dot - mn);
        d = d * sc + wt;
        sa.x = fmaf(sa.x, sc, wt * cur.x);
        sa.y = fmaf(sa.y, sc, wt * cur.y);
        sa.z = fmaf(sa.z, sc, wt * cur.z);
        sa.w = fmaf(sa.w, sc, wt * cur.w);
        m = mn;
        cur = nxt;
        nxt = nn;
    }

    ((float4*)(d_scr + (size_t)(b * NCHUNK + chunk) * H))[tid] = sa;
    if (tid == 0) {
        d_md[(size_t)(b * NCHUNK + chunk) * 2 + 0] = m;
        d_md[(size_t)(b * NCHUNK + chunk) * 2 + 1] = d;
    }
}

// ================= grid combine: ctx[b,h] = sum_c w_c * s_c[h] / D
__global__ void __launch_bounds__(256) combine_kernel() {
    int b = blockIdx.x, q = blockIdx.y;
    int tid = threadIdx.x;
    __shared__ float mb[NCHUNK], db[NCHUNK], wc[NCHUNK];
    if (tid < NCHUNK) {
        mb[tid] = d_md[(size_t)(b * NCHUNK + tid) * 2 + 0];
        db[tid] = d_md[(size_t)(b * NCHUNK + tid) * 2 + 1];
    }
    __syncthreads();
    float M = mb[0];
#pragma unroll
    for (int c = 1; c < NCHUNK; c++) M = fmaxf(M, mb[c]);
    if (tid < NCHUNK) wc[tid] = __expf(mb[tid] - M);
    __syncthreads();
    float D = 0.f;
#pragma unroll
    for (int c = 0; c < NCHUNK; c++) D += wc[c] * db[c];
    float inv = 1.f / D;
    int h = q * 256 + tid;
    float a = 0.f;
#pragma unroll
    for (int c = 0; c < NCHUNK; c++)
        a = fmaf(wc[c], d_scr[(size_t)(b * NCHUNK + c) * H + h], a);
    d_ctx[(size_t)b * H + h] = a * inv;
}

// ================= final GEMM partials: [ctx, h_t] @ Wv, j-chunked
__global__ void __launch_bounds__(256) final_partial_kernel(const float* __restrict__ Wv) {
    int jc = blockIdx.x, bgrp = blockIdx.y;
    int tid = threadIdx.x;          // o
    __shared__ float pa[8][32];
    {
        int bi = tid >> 5, jj = tid & 31;
        int bb = bgrp * 8 + bi;
        int j = jc * 32 + jj;
        pa[bi][jj] = (j < H) ? d_ctx[(size_t)bb * H + j]
                             : d_ht[(size_t)bb * H + (j - H)];
    }
    __syncthreads();
    float acc[8];
#pragma unroll
    for (int bi = 0; bi < 8; bi++) acc[bi] = 0.f;
    const float* wp = Wv + (size_t)(jc * 32) * OUT + tid;
#pragma unroll 8
    for (int jj = 0; jj < 32; jj++) {
        float wv = wp[(size_t)jj * OUT];
#pragma unroll
        for (int bi = 0; bi < 8; bi++) acc[bi] = fmaf(pa[bi][jj], wv, acc[bi]);
    }
#pragma unroll
    for (int bi = 0; bi < 8; bi++)
        d_fp[((size_t)jc * B + bgrp * 8 + bi) * OUT + tid] = acc[bi];
}

// ================= final reduce + bias + tanh
__global__ void __launch_bounds__(256) final_reduce_kernel(const float* __restrict__ bv,
                                                           float* __restrict__ out) {
    int b = blockIdx.x;
    int o = threadIdx.x;
    float a = bv[o];
#pragma unroll 16
    for (int jc = 0; jc < JC; jc++) a += d_fp[((size_t)jc * B + b) * OUT + o];
    out[(size_t)b * OUT + o] = tanhf(a);
}

extern "C" void kernel_launch(void* const* d_in, const int* in_sizes, int n_in,
                              void* d_out, int out_size) {
    const float* hs = (const float*)d_in[0];
    const float* W1 = (const float*)d_in[1];
    const float* b1 = (const float*)d_in[2];
    const float* Wv = (const float*)d_in[3];
    const float* bv = (const float*)d_in[4];
    float* out = (float*)d_out;

    ht_partial_kernel<<<dim3(32, HC), 256>>>(hs, W1);
    ht_reduce_kernel<<<128, 256>>>(b1);
    v_kernel<<<dim3(128, 8), 256>>>(W1);
    main_pass_kernel<<<dim3(NCHUNK, B), 256>>>(hs);
    combine_kernel<<<dim3(B, 4), 256>>>();
    final_partial_kernel<<<dim3(JC, 4), 256>>>(Wv);
    final_reduce_kernel<<<B, OUT>>>(bv, out);
}

// round 4
// speedup vs baseline: 1.5126x; 1.0158x over previous
#include <cuda_runtime.h>
#include <math.h>

#define B   32
#define T   2048
#define H   1024
#define OUT 256

#define CHUNK  64                 // t-rows per block in main pass
#define NCHUNK (T / CHUNK)        // 32 chunks
#define GRP    8                  // rows per group in main pass
#define NGRP   (CHUNK / GRP)      // 8 groups
#define HC     16                 // h-chunks for ht partial (64 each)

// ---- scratch (__device__ globals; no allocation allowed) ----
__device__ float d_htp[HC * B * H];                   // h_t partials
__device__ float d_ht [B * H];                        // h_t
__device__ float d_v  [B * H];                        // v[b] = W1 @ h_t[b]
__device__ float d_scr[(size_t)B * NCHUNK * H];       // per-chunk context partials
__device__ float d_md [(size_t)B * NCHUNK * 2];       // per-chunk (m, d)

// ================= h_t partial: h_t[b,k] += sum_{h in chunk} hs_last[b,h]*W1[h,k]
__global__ void __launch_bounds__(256) ht_partial_kernel(const float* __restrict__ hs,
                                                         const float* __restrict__ W1) {
    int kt = blockIdx.x, hc = blockIdx.y;
    int tid = threadIdx.x;
    int kl = tid & 31, bg = tid >> 5;
    __shared__ float hsl[B][64];
    int h0 = hc * 64;
    for (int i = tid; i < B * 64; i += 256) {
        int b = i >> 6, hh = i & 63;
        hsl[b][hh] = hs[((size_t)b * T + (T - 1)) * H + h0 + hh];
    }
    __syncthreads();
    int k = kt * 32 + kl;
    int b0 = bg * 4;
    float a0 = 0.f, a1 = 0.f, a2 = 0.f, a3 = 0.f;
    const float* w1p = W1 + (size_t)h0 * H + k;
#pragma unroll 16
    for (int hh = 0; hh < 64; hh++) {
        float w = w1p[(size_t)hh * H];
        a0 = fmaf(hsl[b0 + 0][hh], w, a0);
        a1 = fmaf(hsl[b0 + 1][hh], w, a1);
        a2 = fmaf(hsl[b0 + 2][hh], w, a2);
        a3 = fmaf(hsl[b0 + 3][hh], w, a3);
    }
    d_htp[((size_t)hc * B + b0 + 0) * H + k] = a0;
    d_htp[((size_t)hc * B + b0 + 1) * H + k] = a1;
    d_htp[((size_t)hc * B + b0 + 2) * H + k] = a2;
    d_htp[((size_t)hc * B + b0 + 3) * H + k] = a3;
}

// ================= h_t reduce (+ bias b1): 32768 outputs
__global__ void __launch_bounds__(256) ht_reduce_kernel(const float* __restrict__ b1) {
    int idx = blockIdx.x * 256 + threadIdx.x;
    int b = idx >> 10, k = idx & (H - 1);
    float a = b1[k];
#pragma unroll
    for (int hc = 0; hc < HC; hc++) a += d_htp[((size_t)hc * B + b) * H + k];
    d_ht[(size_t)b * H + k] = a;
}

// ================= v[b,h] = dot(W1 row h, h_t[b])
__global__ void __launch_bounds__(256) v_kernel(const float* __restrict__ W1) {
    int ht8 = blockIdx.x, bg = blockIdx.y;
    int tid = threadIdx.x;
    int w = tid >> 5, lane = tid & 31;
    __shared__ float hts[4][H];
    for (int i = tid; i < 4 * H; i += 256) {
        int bi = i >> 10, k = i & (H - 1);
        hts[bi][k] = d_ht[(size_t)(bg * 4 + bi) * H + k];
    }
    __syncthreads();
    int h = ht8 * 8 + w;
    const float4* row = (const float4*)(W1 + (size_t)h * H);
    float a0 = 0.f, a1 = 0.f, a2 = 0.f, a3 = 0.f;
#pragma unroll
    for (int ki = 0; ki < 8; ki++) {
        float4 wv = row[ki * 32 + lane];
        int kb = (ki * 32 + lane) * 4;
        float4 t0 = *(const float4*)&hts[0][kb];
        float4 t1 = *(const float4*)&hts[1][kb];
        float4 t2 = *(const float4*)&hts[2][kb];
        float4 t3 = *(const float4*)&hts[3][kb];
        a0 = fmaf(wv.x, t0.x, fmaf(wv.y, t0.y, fmaf(wv.z, t0.z, fmaf(wv.w, t0.w, a0))));
        a1 = fmaf(wv.x, t1.x, fmaf(wv.y, t1.y, fmaf(wv.z, t1.z, fmaf(wv.w, t1.w, a1))));
        a2 = fmaf(wv.x, t2.x, fmaf(wv.y, t2.y, fmaf(wv.z, t2.z, fmaf(wv.w, t2.w, a2))));
        a3 = fmaf(wv.x, t3.x, fmaf(wv.y, t3.y, fmaf(wv.z, t3.z, fmaf(wv.w, t3.w, a3))));
    }
#pragma unroll
    for (int off = 16; off; off >>= 1) {
        a0 += __shfl_xor_sync(0xffffffffu, a0, off);
        a1 += __shfl_xor_sync(0xffffffffu, a1, off);
        a2 += __shfl_xor_sync(0xffffffffu, a2, off);
        a3 += __shfl_xor_sync(0xffffffffu, a3, off);
    }
    if (lane == 0) {
        d_v[(size_t)(bg * 4 + 0) * H + h] = a0;
        d_v[(size_t)(bg * 4 + 1) * H + h] = a1;
        d_v[(size_t)(bg * 4 + 2) * H + h] = a2;
        d_v[(size_t)(bg * 4 + 3) * H + h] = a3;
    }
}

// ================= main streaming pass: grouped rows (8 per barrier)
// grid (NCHUNK, B), 256 threads. Thread tid owns h-slice [4*tid, 4*tid+4).
// Per 8-row group: 8 batched LDG.128 -> 8 pipelined shfl-reduce chains ->
// ONE barrier (double-buffered) -> 8 block-uniform online-softmax updates.
__global__ void __launch_bounds__(256) main_pass_kernel(const float* __restrict__ hs) {
    int chunk = blockIdx.x;
    int b = blockIdx.y;
    int tid = threadIdx.x;
    int w = tid >> 5, lane = tid & 31;

    __shared__ float part[2][GRP][8];

    float4 vr = ((const float4*)(d_v + (size_t)b * H))[tid];
    float4 sa = make_float4(0.f, 0.f, 0.f, 0.f);
    float m = -INFINITY, d = 0.f;

    const float4* base = (const float4*)(hs + ((size_t)b * T + (size_t)chunk * CHUNK) * H) + tid;

#pragma unroll
    for (int g = 0; g < NGRP; g++) {
        float4 val[GRP];
#pragma unroll
        for (int j = 0; j < GRP; j++)
            val[j] = __ldcs(base + (size_t)(g * GRP + j) * (H / 4));

        float p[GRP];
#pragma unroll
        for (int j = 0; j < GRP; j++)
            p[j] = fmaf(val[j].x, vr.x, fmaf(val[j].y, vr.y,
                   fmaf(val[j].z, vr.z, val[j].w * vr.w)));

#pragma unroll
        for (int off = 16; off; off >>= 1) {
#pragma unroll
            for (int j = 0; j < GRP; j++)
                p[j] += __shfl_xor_sync(0xffffffffu, p[j], off);
        }
        if (lane == 0) {
#pragma unroll
            for (int j = 0; j < GRP; j++) part[g & 1][j][w] = p[j];
        }
        __syncthreads();

        float dt[GRP];
#pragma unroll
        for (int j = 0; j < GRP; j++) {
            float4 x = *(const float4*)&part[g & 1][j][0];
            float4 y = *(const float4*)&part[g & 1][j][4];
            dt[j] = ((x.x + x.y) + (x.z + x.w)) + ((y.x + y.y) + (y.z + y.w));
        }
#pragma unroll
        for (int j = 0; j < GRP; j++) {
            float mn = fmaxf(m, dt[j]);
            float sc = __expf(m - mn);      // 0 on first row (m=-inf)
            float wt = __expf(dt[j] - mn);
            d = d * sc + wt;
            sa.x = fmaf(sa.x, sc, wt * val[j].x);
            sa.y = fmaf(sa.y, sc, wt * val[j].y);
            sa.z = fmaf(sa.z, sc, wt * val[j].z);
            sa.w = fmaf(sa.w, sc, wt * val[j].w);
            m = mn;
        }
    }

    ((float4*)(d_scr + (size_t)(b * NCHUNK + chunk) * H))[tid] = sa;
    if (tid == 0) {
        d_md[(size_t)(b * NCHUNK + chunk) * 2 + 0] = m;
        d_md[(size_t)(b * NCHUNK + chunk) * 2 + 1] = d;
    }
}

// ================= fused combine + final GEMM + tanh
// grid (B, 8 o-tiles of 32), 256 threads.
// Block: softmax-combine chunks -> pre=[ctx|h_t] in smem -> 32-col Wv GEMM.
__global__ void __launch_bounds__(256) combine_final_kernel(const float* __restrict__ Wv,
                                                            const float* __restrict__ bv,
                                                            float* __restrict__ out) {
    int b = blockIdx.x, ot = blockIdx.y;
    int tid = threadIdx.x;

    __shared__ float pre[2 * H];
    __shared__ float wcs[NCHUNK];
    __shared__ float mdsh[2 * NCHUNK];
    __shared__ float red[8][32];

    if (tid < 2 * NCHUNK) mdsh[tid] = d_md[(size_t)b * NCHUNK * 2 + tid];
    __syncthreads();

    float M = mdsh[0];
#pragma unroll
    for (int c = 1; c < NCHUNK; c++) M = fmaxf(M, mdsh[2 * c]);
    if (tid < NCHUNK) wcs[tid] = __expf(mdsh[2 * tid] - M);
    __syncthreads();
    float D = 0.f;
#pragma unroll
    for (int c = 0; c < NCHUNK; c++) D += wcs[c] * mdsh[2 * c + 1];
    float inv = 1.f / D;

#pragma unroll
    for (int q = 0; q < 4; q++) {
        int h = q * 256 + tid;
        float a = 0.f;
#pragma unroll
        for (int c = 0; c < NCHUNK; c++)
            a = fmaf(wcs[c], d_scr[(size_t)(b * NCHUNK + c) * H + h], a);
        pre[h] = a * inv;
    }
    ((float4*)(pre + H))[tid] = ((const float4*)(d_ht + (size_t)b * H))[tid];
    __syncthreads();

    int o = ot * 32 + (tid & 31);
    int jg = tid >> 5;
    const float* wp = Wv + (size_t)(jg * 256) * OUT + o;
    const float* pp = pre + jg * 256;
    float acc = 0.f;
#pragma unroll 8
    for (int jj = 0; jj < 256; jj++)
        acc = fmaf(pp[jj], wp[(size_t)jj * OUT], acc);
    red[jg][tid & 31] = acc;
    __syncthreads();

    if (tid < 32) {
        float a = bv[ot * 32 + tid];
#pragma unroll
        for (int k = 0; k < 8; k++) a += red[k][tid];
        out[(size_t)b * OUT + ot * 32 + tid] = tanhf(a);
    }
}

extern "C" void kernel_launch(void* const* d_in, const int* in_sizes, int n_in,
                              void* d_out, int out_size) {
    const float* hs = (const float*)d_in[0];
    const float* W1 = (const float*)d_in[1];
    const float* b1 = (const float*)d_in[2];
    const float* Wv = (const float*)d_in[3];
    const float* bv = (const float*)d_in[4];
    float* out = (float*)d_out;

    ht_partial_kernel<<<dim3(32, HC), 256>>>(hs, W1);
    ht_reduce_kernel<<<128, 256>>>(b1);
    v_kernel<<<dim3(128, 8), 256>>>(W1);
    main_pass_kernel<<<dim3(NCHUNK, B), 256>>>(hs);
    combine_final_kernel<<<dim3(B, 8), 256>>>(Wv, bv, out);
}